// round 8
// baseline (speedup 1.0000x reference)
#include <cuda_runtime.h>

// LIF SNN scan: T=1024 timesteps, B*N = 65536 independent columns.
// out layout: [ spikes (T*BN) | v_final (BN) | i_final (BN) ]
// R8: double-buffered phase batching — group 32 LDGs, then 32 compute+STGs —
// so DRAM sees separated read bursts / write bursts (less R/W turnaround),
// instead of per-step interleaved LDG/STG. MLP unchanged (32 in flight).

#define T_STEPS 1024
#define BN      65536
#define HB      32          // half-buffer depth

__global__ __launch_bounds__(64, 4)
void snn_lif_kernel(const float* __restrict__ x, float* __restrict__ out) {
    const int idx = blockIdx.x * blockDim.x + threadIdx.x;  // column id
    const float* xp = x + idx;
    float*       zp = out + idx;

    float v   = 0.0f;   // membrane potential
    float cur = 0.0f;   // synaptic current

    float a[HB], b[HB];

    // prologue: fill buffer a with t = 0..31 (32 LDGs in flight)
    #pragma unroll
    for (int j = 0; j < HB; ++j)
        a[j] = __ldg(xp + (long)j * BN);

    // dt*tau_mem_inv = 0.1, (1 - dt*tau_syn_inv) = 0.8, v_th = 1, v_reset = 0
    for (int t0 = 0; t0 < T_STEPS; t0 += 2 * HB) {
        // phase 1: issue 32 loads for t0+32 .. t0+63 (always in range)
        #pragma unroll
        for (int j = 0; j < HB; ++j)
            b[j] = __ldg(xp + (long)(t0 + HB + j) * BN);

        // phase 2: compute + store 32 steps from buffer a (t0 .. t0+31)
        #pragma unroll
        for (int j = 0; j < HB; ++j) {
            const float xt    = a[j];
            const float v_dec = fmaf(0.1f, cur - v, v);
            const bool  fired = (v_dec > 1.0f);
            zp[(long)(t0 + j) * BN] = fired ? 1.0f : 0.0f;
            v   = fired ? 0.0f : v_dec;
            cur = fmaf(cur, 0.8f, xt);
        }

        // phase 3: issue 32 loads for t0+64 .. t0+95 (skip on last chunk)
        if (t0 + 2 * HB < T_STEPS) {
            #pragma unroll
            for (int j = 0; j < HB; ++j)
                a[j] = __ldg(xp + (long)(t0 + 2 * HB + j) * BN);
        }

        // phase 4: compute + store 32 steps from buffer b (t0+32 .. t0+63)
        #pragma unroll
        for (int j = 0; j < HB; ++j) {
            const float xt    = b[j];
            const float v_dec = fmaf(0.1f, cur - v, v);
            const bool  fired = (v_dec > 1.0f);
            zp[(long)(t0 + HB + j) * BN] = fired ? 1.0f : 0.0f;
            v   = fired ? 0.0f : v_dec;
            cur = fmaf(cur, 0.8f, xt);
        }
    }

    // final state after the full scan
    out[(long)T_STEPS * BN + idx]      = v;
    out[(long)T_STEPS * BN + BN + idx] = cur;
}

extern "C" void kernel_launch(void* const* d_in, const int* in_sizes, int n_in,
                              void* d_out, int out_size) {
    const float* x   = (const float*)d_in[0];
    float*       out = (float*)d_out;
    (void)in_sizes; (void)n_in; (void)out_size;

    snn_lif_kernel<<<BN / 64, 64>>>(x, out);
}

// round 9
// speedup vs baseline: 1.0507x; 1.0507x over previous
#include <cuda_runtime.h>

// LIF SNN scan: T=1024 timesteps, B*N = 65536 independent columns.
// out layout: [ spikes (T*BN) | v_final (BN) | i_final (BN) ]
// R9: rolling prefetch ring (R4/R6 structure, constant 32 loads in flight)
// with float2 (2 columns/thread): halves LSU dispatch ops per byte
// (LDG.64+STG.64 per 2 columns) — LSU was co-binding at ~68us vs 78us total.

#define T_STEPS 1024
#define BN      65536
#define NCOL2   (BN / 2)    // float2 columns
#define PF      32

__global__ __launch_bounds__(64, 4)
void snn_lif_kernel(const float2* __restrict__ x, float2* __restrict__ out) {
    const int idx = blockIdx.x * blockDim.x + threadIdx.x;  // float2-column id
    const float2* xp = x + idx;
    float2*       zp = out + idx;

    float v0 = 0.0f, v1 = 0.0f;     // membrane potentials
    float c0 = 0.0f, c1 = 0.0f;     // synaptic currents

    // prologue: fill the prefetch ring (32 independent LDG.64 in flight)
    float2 xbuf[PF];
    #pragma unroll
    for (int j = 0; j < PF; ++j)
        xbuf[j] = __ldg(xp + (long)j * NCOL2);

    // dt*tau_mem_inv = 0.1, (1 - dt*tau_syn_inv) = 0.8, v_th = 1, v_reset = 0
    for (int t0 = 0; t0 < T_STEPS - PF; t0 += PF) {
        #pragma unroll
        for (int j = 0; j < PF; ++j) {
            const float2 xt = xbuf[j];
            // immediately re-issue this slot for t0+PF+j (ring stays full)
            xbuf[j] = __ldg(xp + (long)(t0 + PF + j) * NCOL2);

            float2 z;

            const float vd0 = fmaf(0.1f, c0 - v0, v0);
            const bool  f0  = (vd0 > 1.0f);
            z.x = f0 ? 1.0f : 0.0f;
            v0  = f0 ? 0.0f : vd0;
            c0  = fmaf(c0, 0.8f, xt.x);

            const float vd1 = fmaf(0.1f, c1 - v1, v1);
            const bool  f1  = (vd1 > 1.0f);
            z.y = f1 ? 1.0f : 0.0f;
            v1  = f1 ? 0.0f : vd1;
            c1  = fmaf(c1, 0.8f, xt.y);

            zp[(long)(t0 + j) * NCOL2] = z;
        }
    }

    // epilogue: last PF steps, no prefetch
    #pragma unroll
    for (int j = 0; j < PF; ++j) {
        const float2 xt = xbuf[j];

        float2 z;

        const float vd0 = fmaf(0.1f, c0 - v0, v0);
        const bool  f0  = (vd0 > 1.0f);
        z.x = f0 ? 1.0f : 0.0f;
        v0  = f0 ? 0.0f : vd0;
        c0  = fmaf(c0, 0.8f, xt.x);

        const float vd1 = fmaf(0.1f, c1 - v1, v1);
        const bool  f1  = (vd1 > 1.0f);
        z.y = f1 ? 1.0f : 0.0f;
        v1  = f1 ? 0.0f : vd1;
        c1  = fmaf(c1, 0.8f, xt.y);

        zp[(long)(T_STEPS - PF + j) * NCOL2] = z;
    }

    // final state after the full scan: v then i, each BN floats (NCOL2 float2)
    float2 vf; vf.x = v0; vf.y = v1;
    float2 cf; cf.x = c0; cf.y = c1;
    out[(long)T_STEPS * NCOL2 + idx]          = vf;
    out[(long)T_STEPS * NCOL2 + NCOL2 + idx]  = cf;
}

extern "C" void kernel_launch(void* const* d_in, const int* in_sizes, int n_in,
                              void* d_out, int out_size) {
    const float2* x   = (const float2*)d_in[0];
    float2*       out = (float2*)d_out;
    (void)in_sizes; (void)n_in; (void)out_size;

    snn_lif_kernel<<<NCOL2 / 64, 64>>>(x, out);
}